// round 3
// baseline (speedup 1.0000x reference)
#include <cuda_runtime.h>
#include <math.h>

#define NN 4096
#define MAXN 256
#define NGRAPH 64

// ---------------- scratch (device globals; no allocation) ----------------
__device__ float g_f[NN * 64];          // per-layer linear features (both heads)
__device__ float g_xbuf[2][NN * 64];    // layer outputs (ping-pong)
__device__ float g_h[NN * 192];         // concat(x1,x2,x3)
__device__ int   g_col[NN * MAXN];      // padded CSR columns
__device__ int   g_cnt[NN];             // row neighbor counts
__device__ float g_s1[2 * NN];          // attention src scores per head (k*NN+row)
__device__ float g_s2[2 * NN];          // attention dst scores per head

// ---------------- GEMM f = x@Wcat + b, with fused attention scores -------
// BM=32, BN=64, BK=32, 256 threads. W layout [2][in][32], b [2][32]=[64].
__device__ __forceinline__ void gemm_attn(
    const float* __restrict__ x, int in,
    const float* __restrict__ W, const float* __restrict__ b,
    const float* __restrict__ a1w, const float* __restrict__ a1b,
    const float* __restrict__ a2w, const float* __restrict__ a2b,
    int bid)
{
    __shared__ float As[32][33];   // [kk][row]
    __shared__ float Ws[32][64];   // [kk][col]
    int row0 = bid * 32;
    int t  = threadIdx.x;
    int tc = t & 15;               // col group: cols 4tc..4tc+3 (one head)
    int tr = t >> 4;               // row group: rows 2tr, 2tr+1
    int lr = t >> 3;               // load row 0..31
    int lc = t & 7;                // load k-group (float4)
    float acc[2][4] = {{0.f,0.f,0.f,0.f},{0.f,0.f,0.f,0.f}};

    for (int kb = 0; kb < in; kb += 32) {
        float4 xv = *(const float4*)&x[(size_t)(row0 + lr) * in + kb + 4 * lc];
        As[4*lc+0][lr] = xv.x; As[4*lc+1][lr] = xv.y;
        As[4*lc+2][lr] = xv.z; As[4*lc+3][lr] = xv.w;
#pragma unroll
        for (int j = 0; j < 2; j++) {
            int u  = t + j * 256;
            int kk = u >> 4, q = u & 15;
            int kh = q >> 3, h = (4 * q) & 31;
            float4 wv = *(const float4*)&W[((size_t)kh * in + kb + kk) * 32 + h];
            *(float4*)&Ws[kk][4 * q] = wv;
        }
        __syncthreads();
#pragma unroll
        for (int kk = 0; kk < 32; kk++) {
            float a0 = As[kk][2*tr], a1 = As[kk][2*tr+1];
            float4 wv = *(float4*)&Ws[kk][4*tc];
            acc[0][0] = fmaf(a0, wv.x, acc[0][0]);
            acc[0][1] = fmaf(a0, wv.y, acc[0][1]);
            acc[0][2] = fmaf(a0, wv.z, acc[0][2]);
            acc[0][3] = fmaf(a0, wv.w, acc[0][3]);
            acc[1][0] = fmaf(a1, wv.x, acc[1][0]);
            acc[1][1] = fmaf(a1, wv.y, acc[1][1]);
            acc[1][2] = fmaf(a1, wv.z, acc[1][2]);
            acc[1][3] = fmaf(a1, wv.w, acc[1][3]);
        }
        __syncthreads();
    }

    // epilogue: bias, store f (float4), fused attention score partials
    int col = 4 * tc;
    float b0 = b[col], b1 = b[col+1], b2 = b[col+2], b3 = b[col+3];
    float w10 = a1w[col], w11 = a1w[col+1], w12 = a1w[col+2], w13 = a1w[col+3];
    float w20 = a2w[col], w21 = a2w[col+1], w22 = a2w[col+2], w23 = a2w[col+3];
    float p1[2], p2[2];
#pragma unroll
    for (int r = 0; r < 2; r++) {
        float f0 = acc[r][0]+b0, f1 = acc[r][1]+b1, f2 = acc[r][2]+b2, f3 = acc[r][3]+b3;
        int row = row0 + 2*tr + r;
        float4 fv = {f0, f1, f2, f3};
        *(float4*)&g_f[(size_t)row * 64 + col] = fv;
        p1[r] = f0*w10 + f1*w11 + f2*w12 + f3*w13;
        p2[r] = f0*w20 + f1*w21 + f2*w22 + f3*w23;
    }
#pragma unroll
    for (int o = 4; o; o >>= 1) {
        p1[0] += __shfl_down_sync(0xffffffffu, p1[0], o, 8);
        p1[1] += __shfl_down_sync(0xffffffffu, p1[1], o, 8);
        p2[0] += __shfl_down_sync(0xffffffffu, p2[0], o, 8);
        p2[1] += __shfl_down_sync(0xffffffffu, p2[1], o, 8);
    }
    if ((tc & 7) == 0) {
        int k = tc >> 3;   // head
#pragma unroll
        for (int r = 0; r < 2; r++) {
            int row = row0 + 2*tr + r;
            g_s1[k * NN + row] = p1[r] + a1b[k];
            g_s2[k * NN + row] = p2[r] + a2b[k];
        }
    }
}

// ---------------- CSR build (float4; ballot ordering) --------------------
__device__ __forceinline__ void csr_body(const float* __restrict__ adj, int wrow) {
    int lane = threadIdx.x & 31;
    const float4* row = (const float4*)(adj + (size_t)wrow * NN);
    int* mycol = g_col + (size_t)wrow * MAXN;
    int base = 0;
#pragma unroll 2
    for (int it = 0; it < 32; it++) {
        float4 v = row[it * 32 + lane];
        int c0 = it * 128 + 4 * lane;
        unsigned lm = (1u << lane) - 1u;
        unsigned m0 = __ballot_sync(0xffffffffu, v.x > 0.0f);
        if (v.x > 0.0f) { int p = base + __popc(m0 & lm); if (p < MAXN) mycol[p] = c0; }
        base += __popc(m0);
        unsigned m1 = __ballot_sync(0xffffffffu, v.y > 0.0f);
        if (v.y > 0.0f) { int p = base + __popc(m1 & lm); if (p < MAXN) mycol[p] = c0 + 1; }
        base += __popc(m1);
        unsigned m2 = __ballot_sync(0xffffffffu, v.z > 0.0f);
        if (v.z > 0.0f) { int p = base + __popc(m2 & lm); if (p < MAXN) mycol[p] = c0 + 2; }
        base += __popc(m2);
        unsigned m3 = __ballot_sync(0xffffffffu, v.w > 0.0f);
        if (v.w > 0.0f) { int p = base + __popc(m3 & lm); if (p < MAXN) mycol[p] = c0 + 3; }
        base += __popc(m3);
    }
    if (lane == 0) g_cnt[wrow] = base < MAXN ? base : MAXN;
}

// ---------------- fused: CSR build + layer-1 GEMM (overlap HBM & FMA) ----
__global__ void fused_csr_gemm1(
    const float* __restrict__ x, const float* __restrict__ adj,
    const float* __restrict__ W, const float* __restrict__ b,
    const float* __restrict__ a1w, const float* __restrict__ a1b,
    const float* __restrict__ a2w, const float* __restrict__ a2b)
{
    if (blockIdx.x < 128) {
        gemm_attn(x, 512, W, b, a1w, a1b, a2w, a2b, blockIdx.x);
    } else {
        int wrow = (blockIdx.x - 128) * 8 + (threadIdx.x >> 5);
        csr_body(adj, wrow);
    }
}

// ---------------- GEMM kernel for layers 2/3 -----------------------------
__global__ void gemm_k(int sel,
    const float* __restrict__ W, const float* __restrict__ b,
    const float* __restrict__ a1w, const float* __restrict__ a1b,
    const float* __restrict__ a2w, const float* __restrict__ a2b)
{
    gemm_attn(g_xbuf[sel], 64, W, b, a1w, a1b, a2w, a2b, blockIdx.x);
}

// ---------------- warp-autonomous sparse softmax aggregation -------------
// One warp per (row, head). No smem, no __syncthreads. Block 256 = 4 rows.
__global__ void __launch_bounds__(256) aggregate(int outsel, int hoff) {
    int wid  = threadIdx.x >> 5;             // 0..7
    int lane = threadIdx.x & 31;
    int i = blockIdx.x * 4 + (wid >> 1);     // row
    int k = wid & 1;                          // head

    int cnt = g_cnt[i];
    float s1 = g_s1[k * NN + i];
    const float* __restrict__ s2 = g_s2 + k * NN;
    const int* __restrict__ mycol = g_col + (size_t)i * MAXN;

    // load neighbor ids + leaky logits into registers (up to 8 chunks of 32)
    int   jreg[8];
    float wreg[8];
    float m = -1e30f;
#pragma unroll
    for (int c = 0; c < 8; c++) {
        int n = c * 32 + lane;
        jreg[c] = 0;
        wreg[c] = 0.f;
        if (n < cnt) {
            int j = mycol[n];
            jreg[c] = j;
            float e = s1 + s2[j];
            e = e > 0.f ? e : 0.01f * e;      // leaky_relu 0.01
            wreg[c] = e;
            m = fmaxf(m, e);
        }
        if ((c + 1) * 32 >= cnt) break;
    }
    // warp max
#pragma unroll
    for (int o = 16; o; o >>= 1) m = fmaxf(m, __shfl_xor_sync(0xffffffffu, m, o));

    // exp + warp sum
    float s = 0.f;
#pragma unroll
    for (int c = 0; c < 8; c++) {
        int n = c * 32 + lane;
        if (n < cnt) {
            float w = __expf(wreg[c] - m);
            wreg[c] = w;
            s += w;
        }
        if ((c + 1) * 32 >= cnt) break;
    }
#pragma unroll
    for (int o = 16; o; o >>= 1) s += __shfl_xor_sync(0xffffffffu, s, o);
    float inv = 1.0f / s;

    // weighted aggregation: broadcast (j, w) from owning lane, coalesced
    // 128B load of this head's feature half, FMA.
    const float* __restrict__ fbase = g_f + k * 32 + lane;
    float acc = 0.f;
#pragma unroll 1
    for (int c = 0; c * 32 < cnt; c++) {
        int lim = cnt - c * 32;
        lim = lim < 32 ? lim : 32;
        int jc = jreg[c];
        float wc = wreg[c];
#pragma unroll 4
        for (int l = 0; l < lim; l++) {
            int   jn = __shfl_sync(0xffffffffu, jc, l);
            float wn = __shfl_sync(0xffffffffu, wc, l);
            acc = fmaf(wn, fbase[(size_t)jn * 64], acc);
        }
    }

    float o = acc * inv;
    o = o > 0.f ? o : 0.f;                    // relu
    g_xbuf[outsel][(size_t)i * 64 + k * 32 + lane] = o;
    g_h[(size_t)i * 192 + hoff + k * 32 + lane] = o;
}

// ---------------- fused segment-mean pool + classifier head --------------
__global__ void pool_head(const int* __restrict__ batch,
                          const float* __restrict__ Wf, const float* __restrict__ bf,
                          float* __restrict__ out) {
    int g = blockIdx.x;   // 64
    int t = threadIdx.x;  // 192
    __shared__ float pooled[192];
    __shared__ int sst, sen;
    if (t == 0) {
        int lo = 0, hi = NN;
        while (lo < hi) { int mid = (lo + hi) >> 1; if (batch[mid] < g) lo = mid + 1; else hi = mid; }
        sst = lo;
        hi = NN;
        while (lo < hi) { int mid = (lo + hi) >> 1; if (batch[mid] < g + 1) lo = mid + 1; else hi = mid; }
        sen = lo;
    }
    __syncthreads();
    float s = 0.f;
    for (int r = sst; r < sen; r++) s += g_h[(size_t)r * 192 + t];
    float c = (float)(sen - sst);
    pooled[t] = s / fmaxf(c, 1.0f);
    __syncthreads();
    if (t < 32) {
        float logit = 0.f, v = -1e30f;
        if (t < 10) {
            float acc = bf[t];
            for (int c2 = 0; c2 < 192; c2++) acc = fmaf(pooled[c2], Wf[c2 * 10 + t], acc);
            logit = acc; v = acc;
        }
#pragma unroll
        for (int o = 16; o; o >>= 1) v = fmaxf(v, __shfl_xor_sync(0xffffffffu, v, o));
        float e = (t < 10) ? __expf(logit - v) : 0.f;
        float sm = e;
#pragma unroll
        for (int o = 16; o; o >>= 1) sm += __shfl_xor_sync(0xffffffffu, sm, o);
        if (t < 10) out[g * 10 + t] = e / sm;
    }
}

// ---------------- launch --------------------------------------------------
extern "C" void kernel_launch(void* const* d_in, const int* in_sizes, int n_in,
                              void* d_out, int out_size) {
    const float* x     = (const float*)d_in[0];
    const float* adj   = (const float*)d_in[1];
    const int*   batch = (const int*)d_in[2];
    const float* W[3]   = {(const float*)d_in[3],  (const float*)d_in[9],  (const float*)d_in[15]};
    const float* b[3]   = {(const float*)d_in[4],  (const float*)d_in[10], (const float*)d_in[16]};
    const float* a1w[3] = {(const float*)d_in[5],  (const float*)d_in[11], (const float*)d_in[17]};
    const float* a1b[3] = {(const float*)d_in[6],  (const float*)d_in[12], (const float*)d_in[18]};
    const float* a2w[3] = {(const float*)d_in[7],  (const float*)d_in[13], (const float*)d_in[19]};
    const float* a2b[3] = {(const float*)d_in[8],  (const float*)d_in[14], (const float*)d_in[20]};
    const float* Wf = (const float*)d_in[21];
    const float* bf = (const float*)d_in[22];
    float* out = (float*)d_out;

    // layer 1 GEMM (blocks 0-127) overlapped with CSR build (blocks 128-639)
    fused_csr_gemm1<<<640, 256>>>(x, adj, W[0], b[0], a1w[0], a1b[0], a2w[0], a2b[0]);
    aggregate<<<NN / 4, 256>>>(0, 0);

    gemm_k<<<128, 256>>>(0, W[1], b[1], a1w[1], a1b[1], a2w[1], a2b[1]);
    aggregate<<<NN / 4, 256>>>(1, 64);

    gemm_k<<<128, 256>>>(1, W[2], b[2], a1w[2], a1b[2], a2w[2], a2b[2]);
    aggregate<<<NN / 4, 256>>>(0, 128);

    pool_head<<<NGRAPH, 192>>>(batch, Wf, bf, out);
}

// round 4
// speedup vs baseline: 1.0653x; 1.0653x over previous
#include <cuda_runtime.h>
#include <math.h>

#define NN 4096
#define MAXN 256
#define NGRAPH 64

// ---------------- scratch (device globals; no allocation) ----------------
__device__ float g_f[NN * 64];          // per-layer linear features (both heads)
__device__ float g_xbuf[2][NN * 64];    // layer outputs (ping-pong)
__device__ float g_h[NN * 192];         // concat(x1,x2,x3)
__device__ int   g_col[NN * MAXN];      // padded CSR columns
__device__ int   g_cnt[NN];             // row neighbor counts
__device__ float g_s1[2 * NN];          // attention src scores per head (k*NN+row)
__device__ float g_s2[2 * NN];          // attention dst scores per head

// ---------------- GEMM f = x@Wcat + b, with fused attention scores -------
// BM=32, BN=64, BK=32, 256 threads. W layout [2][in][32], b [2][32]=[64].
__device__ __forceinline__ void gemm_attn(
    const float* __restrict__ x, int in,
    const float* __restrict__ W, const float* __restrict__ b,
    const float* __restrict__ a1w, const float* __restrict__ a1b,
    const float* __restrict__ a2w, const float* __restrict__ a2b,
    int bid)
{
    __shared__ float As[32][33];   // [kk][row]
    __shared__ float Ws[32][64];   // [kk][col]
    int row0 = bid * 32;
    int t  = threadIdx.x;
    int tc = t & 15;               // col group: cols 4tc..4tc+3 (one head)
    int tr = t >> 4;               // row group: rows 2tr, 2tr+1
    int lr = t >> 3;               // load row 0..31
    int lc = t & 7;                // load k-group (float4)
    float acc[2][4] = {{0.f,0.f,0.f,0.f},{0.f,0.f,0.f,0.f}};

    for (int kb = 0; kb < in; kb += 32) {
        float4 xv = *(const float4*)&x[(size_t)(row0 + lr) * in + kb + 4 * lc];
        As[4*lc+0][lr] = xv.x; As[4*lc+1][lr] = xv.y;
        As[4*lc+2][lr] = xv.z; As[4*lc+3][lr] = xv.w;
#pragma unroll
        for (int j = 0; j < 2; j++) {
            int u  = t + j * 256;
            int kk = u >> 4, q = u & 15;
            int kh = q >> 3, h = (4 * q) & 31;
            float4 wv = *(const float4*)&W[((size_t)kh * in + kb + kk) * 32 + h];
            *(float4*)&Ws[kk][4 * q] = wv;
        }
        __syncthreads();
#pragma unroll
        for (int kk = 0; kk < 32; kk++) {
            float a0 = As[kk][2*tr], a1 = As[kk][2*tr+1];
            float4 wv = *(float4*)&Ws[kk][4*tc];
            acc[0][0] = fmaf(a0, wv.x, acc[0][0]);
            acc[0][1] = fmaf(a0, wv.y, acc[0][1]);
            acc[0][2] = fmaf(a0, wv.z, acc[0][2]);
            acc[0][3] = fmaf(a0, wv.w, acc[0][3]);
            acc[1][0] = fmaf(a1, wv.x, acc[1][0]);
            acc[1][1] = fmaf(a1, wv.y, acc[1][1]);
            acc[1][2] = fmaf(a1, wv.z, acc[1][2]);
            acc[1][3] = fmaf(a1, wv.w, acc[1][3]);
        }
        __syncthreads();
    }

    // epilogue: bias, store f (float4), fused attention score partials
    int col = 4 * tc;
    float b0 = b[col], b1 = b[col+1], b2 = b[col+2], b3 = b[col+3];
    float w10 = a1w[col], w11 = a1w[col+1], w12 = a1w[col+2], w13 = a1w[col+3];
    float w20 = a2w[col], w21 = a2w[col+1], w22 = a2w[col+2], w23 = a2w[col+3];
    float p1[2], p2[2];
#pragma unroll
    for (int r = 0; r < 2; r++) {
        float f0 = acc[r][0]+b0, f1 = acc[r][1]+b1, f2 = acc[r][2]+b2, f3 = acc[r][3]+b3;
        int row = row0 + 2*tr + r;
        float4 fv = {f0, f1, f2, f3};
        *(float4*)&g_f[(size_t)row * 64 + col] = fv;
        p1[r] = f0*w10 + f1*w11 + f2*w12 + f3*w13;
        p2[r] = f0*w20 + f1*w21 + f2*w22 + f3*w23;
    }
#pragma unroll
    for (int o = 4; o; o >>= 1) {
        p1[0] += __shfl_down_sync(0xffffffffu, p1[0], o, 8);
        p1[1] += __shfl_down_sync(0xffffffffu, p1[1], o, 8);
        p2[0] += __shfl_down_sync(0xffffffffu, p2[0], o, 8);
        p2[1] += __shfl_down_sync(0xffffffffu, p2[1], o, 8);
    }
    if ((tc & 7) == 0) {
        int k = tc >> 3;   // head
#pragma unroll
        for (int r = 0; r < 2; r++) {
            int row = row0 + 2*tr + r;
            g_s1[k * NN + row] = p1[r] + a1b[k];
            g_s2[k * NN + row] = p2[r] + a2b[k];
        }
    }
}

// ---------------- CSR build (float4; ballot ordering) --------------------
__device__ __forceinline__ void csr_body(const float* __restrict__ adj, int wrow) {
    int lane = threadIdx.x & 31;
    const float4* row = (const float4*)(adj + (size_t)wrow * NN);
    int* mycol = g_col + (size_t)wrow * MAXN;
    int base = 0;
#pragma unroll 2
    for (int it = 0; it < 32; it++) {
        float4 v = row[it * 32 + lane];
        int c0 = it * 128 + 4 * lane;
        unsigned lm = (1u << lane) - 1u;
        unsigned m0 = __ballot_sync(0xffffffffu, v.x > 0.0f);
        if (v.x > 0.0f) { int p = base + __popc(m0 & lm); if (p < MAXN) mycol[p] = c0; }
        base += __popc(m0);
        unsigned m1 = __ballot_sync(0xffffffffu, v.y > 0.0f);
        if (v.y > 0.0f) { int p = base + __popc(m1 & lm); if (p < MAXN) mycol[p] = c0 + 1; }
        base += __popc(m1);
        unsigned m2 = __ballot_sync(0xffffffffu, v.z > 0.0f);
        if (v.z > 0.0f) { int p = base + __popc(m2 & lm); if (p < MAXN) mycol[p] = c0 + 2; }
        base += __popc(m2);
        unsigned m3 = __ballot_sync(0xffffffffu, v.w > 0.0f);
        if (v.w > 0.0f) { int p = base + __popc(m3 & lm); if (p < MAXN) mycol[p] = c0 + 3; }
        base += __popc(m3);
    }
    if (lane == 0) g_cnt[wrow] = base < MAXN ? base : MAXN;
}

// ---------------- fused: CSR build + layer-1 GEMM (overlap HBM & FMA) ----
__global__ void fused_csr_gemm1(
    const float* __restrict__ x, const float* __restrict__ adj,
    const float* __restrict__ W, const float* __restrict__ b,
    const float* __restrict__ a1w, const float* __restrict__ a1b,
    const float* __restrict__ a2w, const float* __restrict__ a2b)
{
    if (blockIdx.x < 128) {
        gemm_attn(x, 512, W, b, a1w, a1b, a2w, a2b, blockIdx.x);
    } else {
        int wrow = (blockIdx.x - 128) * 8 + (threadIdx.x >> 5);
        csr_body(adj, wrow);
    }
}

// ---------------- GEMM kernel for layers 2/3 -----------------------------
__global__ void gemm_k(int sel,
    const float* __restrict__ W, const float* __restrict__ b,
    const float* __restrict__ a1w, const float* __restrict__ a1b,
    const float* __restrict__ a2w, const float* __restrict__ a2b)
{
    gemm_attn(g_xbuf[sel], 64, W, b, a1w, a1b, a2w, a2b, blockIdx.x);
}

// ---------------- sparse softmax aggregation, smem-staged ----------------
// Block 256 = 8 warps = 4 rows x 2 heads. Per (row,head) warp:
//  phase A: softmax over neighbors (register chunks + warp shuffles)
//  stage:   packed {byte_offset, weight} pairs in smem, zero-padded to 8
//  phase B: hot loop = LDS.64 + coalesced LDG.32 + FMA, unroll 8, no branches
__global__ void __launch_bounds__(256) aggregate(int outsel, int hoff) {
    __shared__ float2 pairs[8][MAXN];     // [warp][n] = {off_bytes, w}
    int wid  = threadIdx.x >> 5;          // 0..7
    int lane = threadIdx.x & 31;
    int i = blockIdx.x * 4 + (wid >> 1);  // row
    int k = wid & 1;                      // head

    int cnt = g_cnt[i];
    int cnt_pad = (cnt + 7) & ~7;
    float s1 = g_s1[k * NN + i];
    const float* __restrict__ s2 = g_s2 + k * NN;
    const int* __restrict__ mycol = g_col + (size_t)i * MAXN;

    // phase A: logits -> max -> exp -> sum (<=8 chunks of 32)
    int   jreg[8];
    float wreg[8];
    int nchunk = (cnt + 31) >> 5;
    float m = -1e30f;
    for (int c = 0; c < nchunk; c++) {
        int n = c * 32 + lane;
        int j = 0; float e = -1e30f;
        if (n < cnt) {
            j = mycol[n];
            e = s1 + s2[j];
            e = e > 0.f ? e : 0.01f * e;   // leaky_relu 0.01
        }
        jreg[c] = j; wreg[c] = e;
        m = fmaxf(m, e);
    }
#pragma unroll
    for (int o = 16; o; o >>= 1) m = fmaxf(m, __shfl_xor_sync(0xffffffffu, m, o));
    float s = 0.f;
    for (int c = 0; c < nchunk; c++) {
        int n = c * 32 + lane;
        float w = (n < cnt) ? __expf(wreg[c] - m) : 0.f;
        wreg[c] = w;
        s += w;
    }
#pragma unroll
    for (int o = 16; o; o >>= 1) s += __shfl_xor_sync(0xffffffffu, s, o);
    float inv = 1.0f / s;

    // stage packed pairs (byte offset of feature row, unnormalized weight)
    for (int c = 0; c < nchunk; c++) {
        int n = c * 32 + lane;
        if (n < cnt_pad) {
            float2 p;
            p.x = __int_as_float(jreg[c] << 8);   // j * 256 bytes
            p.y = wreg[c];                         // 0 for padded slots
            pairs[wid][n] = p;
        }
    }
    __syncthreads();

    // phase B: branch-free gather loop
    const char* __restrict__ fb = (const char*)g_f + k * 128 + lane * 4;
    const float2* __restrict__ pw = pairs[wid];
    float acc = 0.f;
#pragma unroll 1
    for (int n = 0; n < cnt_pad; n += 8) {
#pragma unroll
        for (int u = 0; u < 8; u++) {
            float2 p = pw[n + u];
            int off = __float_as_int(p.x);
            acc = fmaf(p.y, *(const float*)(fb + off), acc);
        }
    }

    float o = acc * inv;
    o = o > 0.f ? o : 0.f;                 // relu
    g_xbuf[outsel][(size_t)i * 64 + k * 32 + lane] = o;
    g_h[(size_t)i * 192 + hoff + k * 32 + lane] = o;
}

// ---------------- fused segment-mean pool + classifier head --------------
__global__ void pool_head(const int* __restrict__ batch,
                          const float* __restrict__ Wf, const float* __restrict__ bf,
                          float* __restrict__ out) {
    int g = blockIdx.x;   // 64
    int t = threadIdx.x;  // 192
    __shared__ float pooled[192];
    __shared__ int sst, sen;
    if (t == 0) {
        int lo = 0, hi = NN;
        while (lo < hi) { int mid = (lo + hi) >> 1; if (batch[mid] < g) lo = mid + 1; else hi = mid; }
        sst = lo;
        hi = NN;
        while (lo < hi) { int mid = (lo + hi) >> 1; if (batch[mid] < g + 1) lo = mid + 1; else hi = mid; }
        sen = lo;
    }
    __syncthreads();
    float s = 0.f;
    for (int r = sst; r < sen; r++) s += g_h[(size_t)r * 192 + t];
    float c = (float)(sen - sst);
    pooled[t] = s / fmaxf(c, 1.0f);
    __syncthreads();
    if (t < 32) {
        float logit = 0.f, v = -1e30f;
        if (t < 10) {
            float acc = bf[t];
            for (int c2 = 0; c2 < 192; c2++) acc = fmaf(pooled[c2], Wf[c2 * 10 + t], acc);
            logit = acc; v = acc;
        }
#pragma unroll
        for (int o = 16; o; o >>= 1) v = fmaxf(v, __shfl_xor_sync(0xffffffffu, v, o));
        float e = (t < 10) ? __expf(logit - v) : 0.f;
        float sm = e;
#pragma unroll
        for (int o = 16; o; o >>= 1) sm += __shfl_xor_sync(0xffffffffu, sm, o);
        if (t < 10) out[g * 10 + t] = e / sm;
    }
}

// ---------------- launch --------------------------------------------------
extern "C" void kernel_launch(void* const* d_in, const int* in_sizes, int n_in,
                              void* d_out, int out_size) {
    const float* x     = (const float*)d_in[0];
    const float* adj   = (const float*)d_in[1];
    const int*   batch = (const int*)d_in[2];
    const float* W[3]   = {(const float*)d_in[3],  (const float*)d_in[9],  (const float*)d_in[15]};
    const float* b[3]   = {(const float*)d_in[4],  (const float*)d_in[10], (const float*)d_in[16]};
    const float* a1w[3] = {(const float*)d_in[5],  (const float*)d_in[11], (const float*)d_in[17]};
    const float* a1b[3] = {(const float*)d_in[6],  (const float*)d_in[12], (const float*)d_in[18]};
    const float* a2w[3] = {(const float*)d_in[7],  (const float*)d_in[13], (const float*)d_in[19]};
    const float* a2b[3] = {(const float*)d_in[8],  (const float*)d_in[14], (const float*)d_in[20]};
    const float* Wf = (const float*)d_in[21];
    const float* bf = (const float*)d_in[22];
    float* out = (float*)d_out;

    // layer 1 GEMM (blocks 0-127) overlapped with CSR build (blocks 128-639)
    fused_csr_gemm1<<<640, 256>>>(x, adj, W[0], b[0], a1w[0], a1b[0], a2w[0], a2b[0]);
    aggregate<<<NN / 4, 256>>>(0, 0);

    gemm_k<<<128, 256>>>(0, W[1], b[1], a1w[1], a1b[1], a2w[1], a2b[1]);
    aggregate<<<NN / 4, 256>>>(1, 64);

    gemm_k<<<128, 256>>>(1, W[2], b[2], a1w[2], a1b[2], a2w[2], a2b[2]);
    aggregate<<<NN / 4, 256>>>(0, 128);

    pool_head<<<NGRAPH, 192>>>(batch, Wf, bf, out);
}

// round 5
// speedup vs baseline: 1.1722x; 1.1003x over previous
#include <cuda_runtime.h>
#include <math.h>

#define NN 4096
#define MAXN 256
#define NGRAPH 64

// ---------------- scratch (device globals; no allocation) ----------------
__device__ float g_f[NN * 64];          // per-layer linear features (both heads)
__device__ float g_xbuf[2][NN * 64];    // layer outputs (ping-pong)
__device__ float g_h[NN * 192];         // concat(x1,x2,x3)
__device__ int   g_col[NN * MAXN];      // padded CSR columns
__device__ int   g_cnt[NN];             // row neighbor counts
__device__ float g_s1[2 * NN];          // attention src scores per head (k*NN+row)
__device__ float g_s2[2 * NN];          // attention dst scores per head

// ---------------- GEMM f = x@Wcat + b, with fused attention scores -------
// BM=32, BN=64, BK=32, 256 threads. W layout [2][in][32], b [2][32]=[64].
__device__ __forceinline__ void gemm_attn(
    const float* __restrict__ x, int in,
    const float* __restrict__ W, const float* __restrict__ b,
    const float* __restrict__ a1w, const float* __restrict__ a1b,
    const float* __restrict__ a2w, const float* __restrict__ a2b,
    int bid)
{
    __shared__ float As[32][33];   // [kk][row]
    __shared__ float Ws[32][64];   // [kk][col]
    int row0 = bid * 32;
    int t  = threadIdx.x;
    int tc = t & 15;               // col group: cols 4tc..4tc+3 (one head)
    int tr = t >> 4;               // row group: rows 2tr, 2tr+1
    int lr = t >> 3;               // load row 0..31
    int lc = t & 7;                // load k-group (float4)
    float acc[2][4] = {{0.f,0.f,0.f,0.f},{0.f,0.f,0.f,0.f}};

    for (int kb = 0; kb < in; kb += 32) {
        float4 xv = *(const float4*)&x[(size_t)(row0 + lr) * in + kb + 4 * lc];
        As[4*lc+0][lr] = xv.x; As[4*lc+1][lr] = xv.y;
        As[4*lc+2][lr] = xv.z; As[4*lc+3][lr] = xv.w;
#pragma unroll
        for (int j = 0; j < 2; j++) {
            int u  = t + j * 256;
            int kk = u >> 4, q = u & 15;
            int kh = q >> 3, h = (4 * q) & 31;
            float4 wv = *(const float4*)&W[((size_t)kh * in + kb + kk) * 32 + h];
            *(float4*)&Ws[kk][4 * q] = wv;
        }
        __syncthreads();
#pragma unroll
        for (int kk = 0; kk < 32; kk++) {
            float a0 = As[kk][2*tr], a1 = As[kk][2*tr+1];
            float4 wv = *(float4*)&Ws[kk][4*tc];
            acc[0][0] = fmaf(a0, wv.x, acc[0][0]);
            acc[0][1] = fmaf(a0, wv.y, acc[0][1]);
            acc[0][2] = fmaf(a0, wv.z, acc[0][2]);
            acc[0][3] = fmaf(a0, wv.w, acc[0][3]);
            acc[1][0] = fmaf(a1, wv.x, acc[1][0]);
            acc[1][1] = fmaf(a1, wv.y, acc[1][1]);
            acc[1][2] = fmaf(a1, wv.z, acc[1][2]);
            acc[1][3] = fmaf(a1, wv.w, acc[1][3]);
        }
        __syncthreads();
    }

    // epilogue: bias, store f (float4), fused attention score partials
    int col = 4 * tc;
    float b0 = b[col], b1 = b[col+1], b2 = b[col+2], b3 = b[col+3];
    float w10 = a1w[col], w11 = a1w[col+1], w12 = a1w[col+2], w13 = a1w[col+3];
    float w20 = a2w[col], w21 = a2w[col+1], w22 = a2w[col+2], w23 = a2w[col+3];
    float p1[2], p2[2];
#pragma unroll
    for (int r = 0; r < 2; r++) {
        float f0 = acc[r][0]+b0, f1 = acc[r][1]+b1, f2 = acc[r][2]+b2, f3 = acc[r][3]+b3;
        int row = row0 + 2*tr + r;
        float4 fv = {f0, f1, f2, f3};
        *(float4*)&g_f[(size_t)row * 64 + col] = fv;
        p1[r] = f0*w10 + f1*w11 + f2*w12 + f3*w13;
        p2[r] = f0*w20 + f1*w21 + f2*w22 + f3*w23;
    }
#pragma unroll
    for (int o = 4; o; o >>= 1) {
        p1[0] += __shfl_down_sync(0xffffffffu, p1[0], o, 8);
        p1[1] += __shfl_down_sync(0xffffffffu, p1[1], o, 8);
        p2[0] += __shfl_down_sync(0xffffffffu, p2[0], o, 8);
        p2[1] += __shfl_down_sync(0xffffffffu, p2[1], o, 8);
    }
    if ((tc & 7) == 0) {
        int k = tc >> 3;   // head
#pragma unroll
        for (int r = 0; r < 2; r++) {
            int row = row0 + 2*tr + r;
            g_s1[k * NN + row] = p1[r] + a1b[k];
            g_s2[k * NN + row] = p2[r] + a2b[k];
        }
    }
}

// ---------------- CSR build (float4; ballot ordering) --------------------
__device__ __forceinline__ void csr_body(const float* __restrict__ adj, int wrow) {
    int lane = threadIdx.x & 31;
    const float4* row = (const float4*)(adj + (size_t)wrow * NN);
    int* mycol = g_col + (size_t)wrow * MAXN;
    int base = 0;
#pragma unroll 2
    for (int it = 0; it < 32; it++) {
        float4 v = row[it * 32 + lane];
        int c0 = it * 128 + 4 * lane;
        unsigned lm = (1u << lane) - 1u;
        unsigned m0 = __ballot_sync(0xffffffffu, v.x > 0.0f);
        if (v.x > 0.0f) { int p = base + __popc(m0 & lm); if (p < MAXN) mycol[p] = c0; }
        base += __popc(m0);
        unsigned m1 = __ballot_sync(0xffffffffu, v.y > 0.0f);
        if (v.y > 0.0f) { int p = base + __popc(m1 & lm); if (p < MAXN) mycol[p] = c0 + 1; }
        base += __popc(m1);
        unsigned m2 = __ballot_sync(0xffffffffu, v.z > 0.0f);
        if (v.z > 0.0f) { int p = base + __popc(m2 & lm); if (p < MAXN) mycol[p] = c0 + 2; }
        base += __popc(m2);
        unsigned m3 = __ballot_sync(0xffffffffu, v.w > 0.0f);
        if (v.w > 0.0f) { int p = base + __popc(m3 & lm); if (p < MAXN) mycol[p] = c0 + 3; }
        base += __popc(m3);
    }
    if (lane == 0) g_cnt[wrow] = base < MAXN ? base : MAXN;
}

// ---------------- fused: CSR build + layer-1 GEMM (overlap HBM & FMA) ----
__global__ void fused_csr_gemm1(
    const float* __restrict__ x, const float* __restrict__ adj,
    const float* __restrict__ W, const float* __restrict__ b,
    const float* __restrict__ a1w, const float* __restrict__ a1b,
    const float* __restrict__ a2w, const float* __restrict__ a2b)
{
    if (blockIdx.x < 128) {
        gemm_attn(x, 512, W, b, a1w, a1b, a2w, a2b, blockIdx.x);
    } else {
        int wrow = (blockIdx.x - 128) * 8 + (threadIdx.x >> 5);
        csr_body(adj, wrow);
    }
}

// ---------------- GEMM kernel for layers 2/3 -----------------------------
__global__ void gemm_k(int sel,
    const float* __restrict__ W, const float* __restrict__ b,
    const float* __restrict__ a1w, const float* __restrict__ a1b,
    const float* __restrict__ a2w, const float* __restrict__ a2b)
{
    gemm_attn(g_xbuf[sel], 64, W, b, a1w, a1b, a2w, a2b, blockIdx.x);
}

// ---------------- sparse softmax aggregation, float4 gather --------------
// Block 256 = 8 warps = 4 rows x 2 heads. Warp layout: lane = (q, fe),
// q = lane>>3 (neighbor stream 0..3), fe = lane&7 (float4 feature slot).
// Per iteration a warp consumes 4 neighbors x 32 features via LDG.128.
__global__ void __launch_bounds__(256) aggregate(int outsel, int hoff) {
    __shared__ float2 pairs[8][MAXN];     // [warp][n] = {byte_off, w}
    int wid  = threadIdx.x >> 5;          // 0..7
    int lane = threadIdx.x & 31;
    int i = blockIdx.x * 4 + (wid >> 1);  // row
    int k = wid & 1;                      // head

    int cnt = g_cnt[i];
    float s1 = g_s1[k * NN + i];
    const float* __restrict__ s2 = g_s2 + k * NN;
    const int* __restrict__ mycol = g_col + (size_t)i * MAXN;

    // phase A: logits -> max -> exp -> sum (<=8 chunks of 32)
    int   jreg[8];
    float wreg[8];
    int nchunk = (cnt + 31) >> 5;
    float m = -1e30f;
    for (int c = 0; c < nchunk; c++) {
        int n = c * 32 + lane;
        int j = 0; float e = -1e30f;
        if (n < cnt) {
            j = mycol[n];
            e = s1 + s2[j];
            e = e > 0.f ? e : 0.01f * e;   // leaky_relu 0.01
        }
        jreg[c] = j; wreg[c] = e;
        m = fmaxf(m, e);
    }
#pragma unroll
    for (int o = 16; o; o >>= 1) m = fmaxf(m, __shfl_xor_sync(0xffffffffu, m, o));
    float s = 0.f;
    for (int c = 0; c < nchunk; c++) {
        int n = c * 32 + lane;
        float w = (n < cnt) ? __expf(wreg[c] - m) : 0.f;
        wreg[c] = w;
        s += w;
    }
#pragma unroll
    for (int o = 16; o; o >>= 1) s += __shfl_xor_sync(0xffffffffu, s, o);
    float inv = 1.0f / s;

    // stage packed pairs; head offset baked in; zero-weight padding to x4
    int cnt4 = (cnt + 3) & ~3;
    int kbase = k * 128;                   // byte offset of head half
    for (int c = 0; c < nchunk; c++) {
        int n = c * 32 + lane;
        if (n < cnt4) {
            float2 p;
            p.x = __int_as_float((jreg[c] << 8) + kbase);
            p.y = wreg[c];                 // 0 for padded slots
            pairs[wid][n] = p;
        }
    }
    __syncwarp();

    // phase B: 4 neighbors / iteration, LDG.128 per lane
    int q  = lane >> 3;                    // neighbor stream
    int fe = lane & 7;                     // float4 slot
    const char* __restrict__ fb = (const char*)g_f + fe * 16;
    const float2* __restrict__ pw = pairs[wid];
    float4 acc = {0.f, 0.f, 0.f, 0.f};
#pragma unroll 2
    for (int n = q; n < cnt4; n += 4) {
        float2 p = pw[n];
        float4 fv = *(const float4*)(fb + __float_as_int(p.x));
        acc.x = fmaf(p.y, fv.x, acc.x);
        acc.y = fmaf(p.y, fv.y, acc.y);
        acc.z = fmaf(p.y, fv.z, acc.z);
        acc.w = fmaf(p.y, fv.w, acc.w);
    }
    // reduce across the 4 neighbor streams (lanes differing in bits 3,4)
#pragma unroll
    for (int o = 8; o <= 16; o <<= 1) {
        acc.x += __shfl_xor_sync(0xffffffffu, acc.x, o);
        acc.y += __shfl_xor_sync(0xffffffffu, acc.y, o);
        acc.z += __shfl_xor_sync(0xffffffffu, acc.z, o);
        acc.w += __shfl_xor_sync(0xffffffffu, acc.w, o);
    }
    if (q == 0) {
        float4 o4;
        o4.x = fmaxf(acc.x * inv, 0.f);
        o4.y = fmaxf(acc.y * inv, 0.f);
        o4.z = fmaxf(acc.z * inv, 0.f);
        o4.w = fmaxf(acc.w * inv, 0.f);
        *(float4*)&g_xbuf[outsel][(size_t)i * 64 + k * 32 + fe * 4] = o4;
        *(float4*)&g_h[(size_t)i * 192 + hoff + k * 32 + fe * 4] = o4;
    }
}

// ---------------- fused segment-mean pool + classifier head --------------
__global__ void pool_head(const int* __restrict__ batch,
                          const float* __restrict__ Wf, const float* __restrict__ bf,
                          float* __restrict__ out) {
    int g = blockIdx.x;   // 64
    int t = threadIdx.x;  // 192
    __shared__ float pooled[192];
    __shared__ int sst, sen;
    if (t == 0) {
        int lo = 0, hi = NN;
        while (lo < hi) { int mid = (lo + hi) >> 1; if (batch[mid] < g) lo = mid + 1; else hi = mid; }
        sst = lo;
        hi = NN;
        while (lo < hi) { int mid = (lo + hi) >> 1; if (batch[mid] < g + 1) lo = mid + 1; else hi = mid; }
        sen = lo;
    }
    __syncthreads();
    float s = 0.f;
    for (int r = sst; r < sen; r++) s += g_h[(size_t)r * 192 + t];
    float c = (float)(sen - sst);
    pooled[t] = s / fmaxf(c, 1.0f);
    __syncthreads();
    if (t < 32) {
        float logit = 0.f, v = -1e30f;
        if (t < 10) {
            float acc = bf[t];
            for (int c2 = 0; c2 < 192; c2++) acc = fmaf(pooled[c2], Wf[c2 * 10 + t], acc);
            logit = acc; v = acc;
        }
#pragma unroll
        for (int o = 16; o; o >>= 1) v = fmaxf(v, __shfl_xor_sync(0xffffffffu, v, o));
        float e = (t < 10) ? __expf(logit - v) : 0.f;
        float sm = e;
#pragma unroll
        for (int o = 16; o; o >>= 1) sm += __shfl_xor_sync(0xffffffffu, sm, o);
        if (t < 10) out[g * 10 + t] = e / sm;
    }
}

// ---------------- launch --------------------------------------------------
extern "C" void kernel_launch(void* const* d_in, const int* in_sizes, int n_in,
                              void* d_out, int out_size) {
    const float* x     = (const float*)d_in[0];
    const float* adj   = (const float*)d_in[1];
    const int*   batch = (const int*)d_in[2];
    const float* W[3]   = {(const float*)d_in[3],  (const float*)d_in[9],  (const float*)d_in[15]};
    const float* b[3]   = {(const float*)d_in[4],  (const float*)d_in[10], (const float*)d_in[16]};
    const float* a1w[3] = {(const float*)d_in[5],  (const float*)d_in[11], (const float*)d_in[17]};
    const float* a1b[3] = {(const float*)d_in[6],  (const float*)d_in[12], (const float*)d_in[18]};
    const float* a2w[3] = {(const float*)d_in[7],  (const float*)d_in[13], (const float*)d_in[19]};
    const float* a2b[3] = {(const float*)d_in[8],  (const float*)d_in[14], (const float*)d_in[20]};
    const float* Wf = (const float*)d_in[21];
    const float* bf = (const float*)d_in[22];
    float* out = (float*)d_out;

    // layer 1 GEMM (blocks 0-127) overlapped with CSR build (blocks 128-639)
    fused_csr_gemm1<<<640, 256>>>(x, adj, W[0], b[0], a1w[0], a1b[0], a2w[0], a2b[0]);
    aggregate<<<NN / 4, 256>>>(0, 0);

    gemm_k<<<128, 256>>>(0, W[1], b[1], a1w[1], a1b[1], a2w[1], a2b[1]);
    aggregate<<<NN / 4, 256>>>(1, 64);

    gemm_k<<<128, 256>>>(1, W[2], b[2], a1w[2], a1b[2], a2w[2], a2b[2]);
    aggregate<<<NN / 4, 256>>>(0, 128);

    pool_head<<<NGRAPH, 192>>>(batch, Wf, bf, out);
}